// round 4
// baseline (speedup 1.0000x reference)
#include <cuda_runtime.h>
#include <cuda_bf16.h>
#include <math.h>

typedef unsigned long long ull;

#define TT 128
#define BB 64
#define SS 2
#define DD 1024
#define D3 3072
#define SLABQ 32768          /* ull per state slab: [512 kp][64 b] */

// state in PI layout: pair p of dims (2p,2p+1) at [p][b], packed float2-in-ull
__device__ float d_giU_g[(size_t)TT * D3 * BB];   // [t][j][b], bih included
__device__ float d_giU_p[(size_t)TT * D3 * BB];
__device__ ull   d_gh[(size_t)(TT + 1) * SLABQ];  // slab 0 zeros, slab t+1 = g_t
__device__ ull   d_xA[SLABQ];                     // party[speaker_t] (pre-update)
__device__ ull   d_ctx[SLABQ];
__device__ ull   d_qnew[SLABQ];
__device__ ull   d_ePI[2 * SLABQ];                // emotion ping-pong
__device__ ull   d_par[SS * SLABQ];               // party slots
__device__ float d_scores[TT * BB];
__device__ int   d_spk[TT * BB];

__device__ __forceinline__ ull pk2(float lo, float hi) {
    ull r; asm("mov.b64 %0, {%1, %2};" : "=l"(r) : "f"(lo), "f"(hi)); return r;
}
__device__ __forceinline__ ull dup2(float v) { return pk2(v, v); }
__device__ __forceinline__ void upk2(ull v, float& lo, float& hi) {
    asm("mov.b64 {%0, %1}, %2;" : "=f"(lo), "=f"(hi) : "l"(v));
}
__device__ __forceinline__ ull f2fma(ull a, ull b, ull c) {
    ull d; asm("fma.rn.f32x2 %0, %1, %2, %3;" : "=l"(d) : "l"(a), "l"(b), "l"(c)); return d;
}
__device__ __forceinline__ ull f2mul(ull a, ull b) {
    ull d; asm("mul.rn.f32x2 %0, %1, %2;" : "=l"(d) : "l"(a), "l"(b)); return d;
}
__device__ __forceinline__ float hsum(ull v) { float lo, hi; upk2(v, lo, hi); return lo + hi; }
__device__ __forceinline__ float sigf(float x) { return 1.f / (1.f + __expf(-x)); }

// ---------------------------------------------------------------------------
__global__ void init_kernel(const float* __restrict__ speakers) {
    int i = blockIdx.x * blockDim.x + threadIdx.x;      // 640*256 = 163840
    if (i < 32768) d_gh[i] = 0ull;
    else if (i < 65536) d_xA[i - 32768] = 0ull;
    else if (i < 98304) d_ePI[i - 65536] = 0ull;
    else if (i < 163840) d_par[i - 98304] = 0ull;
    if (i < TT * BB) {
        const float* sp = speakers + (size_t)i * SS;
        int best = 0; float bv = sp[0];
        #pragma unroll
        for (int s = 1; s < SS; s++) if (sp[s] > bv) { bv = sp[s]; best = s; }
        d_spk[i] = best;
    }
}

// ---------------------------------------------------------------------------
// precompute: out[t][j][b] = sum_k W[j][k]*X[t*64+b][k] + bias[j]
// W:(3072 x 2048) cols [0,1024); X:(8192 x 1024). f32x2 packed over j-pairs.
// grid (24 j-tiles, 64 row-tiles, 2 {g,p}), 256 thr, BJ=128 BR=128 BK=16.
// ---------------------------------------------------------------------------
__global__ void __launch_bounds__(256) precompute_kernel(
    const float* __restrict__ X,
    const float* __restrict__ Wg, const float* __restrict__ big,
    const float* __restrict__ Wp, const float* __restrict__ bip)
{
    const float* W    = blockIdx.z ? Wp : Wg;
    const float* bias = blockIdx.z ? bip : big;
    float* out        = blockIdx.z ? d_giU_p : d_giU_g;

    __shared__ float Ws[16][128];
    __shared__ float Xs[16][128];

    int tid = threadIdx.x;
    int tx = tid & 31, ty = tid >> 5;
    int j0 = blockIdx.x * 128;
    int r0 = blockIdx.y * 128;

    ull acc[8][4];
    #pragma unroll
    for (int p = 0; p < 8; p++)
        #pragma unroll
        for (int r = 0; r < 4; r++) acc[p][r] = 0ull;

    for (int k0 = 0; k0 < 1024; k0 += 16) {
        #pragma unroll
        for (int i = 0; i < 2; i++) {
            int f = tid * 2 + i;               // 0..511
            int rr = f >> 2, kc = (f & 3) * 4;
            float4 v = *(const float4*)&W[(size_t)(j0 + rr) * 2048 + k0 + kc];
            Ws[kc + 0][rr] = v.x; Ws[kc + 1][rr] = v.y;
            Ws[kc + 2][rr] = v.z; Ws[kc + 3][rr] = v.w;
            float4 u = *(const float4*)&X[(size_t)(r0 + rr) * 1024 + k0 + kc];
            Xs[kc + 0][rr] = u.x; Xs[kc + 1][rr] = u.y;
            Xs[kc + 2][rr] = u.z; Xs[kc + 3][rr] = u.w;
        }
        __syncthreads();
        #pragma unroll
        for (int k = 0; k < 16; k++) {
            ulonglong2 w0 = *(const ulonglong2*)&Ws[k][ty * 16 + 0];
            ulonglong2 w1 = *(const ulonglong2*)&Ws[k][ty * 16 + 4];
            ulonglong2 w2 = *(const ulonglong2*)&Ws[k][ty * 16 + 8];
            ulonglong2 w3 = *(const ulonglong2*)&Ws[k][ty * 16 + 12];
            ull wj[8] = {w0.x, w0.y, w1.x, w1.y, w2.x, w2.y, w3.x, w3.y};
            float4 xv = *(const float4*)&Xs[k][tx * 4];
            ull xx[4] = {dup2(xv.x), dup2(xv.y), dup2(xv.z), dup2(xv.w)};
            #pragma unroll
            for (int p = 0; p < 8; p++)
                #pragma unroll
                for (int r = 0; r < 4; r++)
                    acc[p][r] = f2fma(wj[p], xx[r], acc[p][r]);
        }
        __syncthreads();
    }
    int rbase = r0 + tx * 4;                    // 4 rows, never crossing a t-boundary
    int tt = rbase >> 6, b0 = rbase & 63;
    #pragma unroll
    for (int p = 0; p < 8; p++) {
        int jj = j0 + ty * 16 + p * 2;
        float lo[4], hi[4];
        #pragma unroll
        for (int r = 0; r < 4; r++) upk2(acc[p][r], lo[r], hi[r]);
        float bl = bias[jj], bh = bias[jj + 1];
        float4 vlo = make_float4(lo[0]+bl, lo[1]+bl, lo[2]+bl, lo[3]+bl);
        float4 vhi = make_float4(hi[0]+bh, hi[1]+bh, hi[2]+bh, hi[3]+bh);
        *(float4*)&out[((size_t)tt * D3 + jj) * 64 + b0]       = vlo;
        *(float4*)&out[((size_t)tt * D3 + jj + 1) * 64 + b0]   = vhi;
    }
}

// ---------------------------------------------------------------------------
// GRU dual-unit dot core. Warp: units u0,u0+1 (u0 even), lanes = batch b0 and
// b0+32. Accumulators a[uu*12 + bh*6 + {0..2: x-gates r,z,n, 3..5: h-gates}].
// ---------------------------------------------------------------------------
__device__ __forceinline__ void gru24(
    const float* __restrict__ Wx, int wxs, int xoff,
    const float* __restrict__ Wh,
    int u0, int b0,
    const ull* __restrict__ xq, const ull* __restrict__ hq, ull* a)
{
    const ulonglong2* wp[12];
    #pragma unroll
    for (int uu = 0; uu < 2; uu++)
        #pragma unroll
        for (int g = 0; g < 3; g++) {
            wp[uu*6 + g]     = (const ulonglong2*)(Wx + (size_t)(g*1024 + u0 + uu) * wxs + xoff);
            wp[uu*6 + 3 + g] = (const ulonglong2*)(Wh + (size_t)(g*1024 + u0 + uu) * 1024);
        }
    const ull* xa = xq + b0;
    const ull* xb = xq + b0 + 32;
    const ull* ha = hq + b0;
    const ull* hb = hq + b0 + 32;
    #pragma unroll
    for (int i = 0; i < 24; i++) a[i] = 0ull;

    #pragma unroll 2
    for (int i = 0; i < 256; i++) {
        ull x00 = xa[(2*i)   * 64];
        ull x01 = xb[(2*i)   * 64];
        ull x10 = xa[(2*i+1) * 64];
        ull x11 = xb[(2*i+1) * 64];
        ull h00 = ha[(2*i)   * 64];
        ull h01 = hb[(2*i)   * 64];
        ull h10 = ha[(2*i+1) * 64];
        ull h11 = hb[(2*i+1) * 64];
        #pragma unroll
        for (int uu = 0; uu < 2; uu++)
            #pragma unroll
            for (int g = 0; g < 3; g++) {
                ulonglong2 wx = wp[uu*6 + g][i];
                ulonglong2 wh = wp[uu*6 + 3 + g][i];
                a[uu*12 + g]     = f2fma(wx.x, x00, a[uu*12 + g]);
                a[uu*12 + g]     = f2fma(wx.y, x10, a[uu*12 + g]);
                a[uu*12 + 6 + g] = f2fma(wx.x, x01, a[uu*12 + 6 + g]);
                a[uu*12 + 6 + g] = f2fma(wx.y, x11, a[uu*12 + 6 + g]);
                a[uu*12 + 3 + g] = f2fma(wh.x, h00, a[uu*12 + 3 + g]);
                a[uu*12 + 3 + g] = f2fma(wh.y, h10, a[uu*12 + 3 + g]);
                a[uu*12 + 9 + g] = f2fma(wh.x, h01, a[uu*12 + 9 + g]);
                a[uu*12 + 9 + g] = f2fma(wh.y, h11, a[uu*12 + 9 + g]);
            }
    }
}

// gate math; giR/Z/N already include x-projection + bih (phases A/B) or = bih (C)
__device__ __forceinline__ float gout(const ull* a, float giR, float giZ, float giN,
                                      float bhr, float bhz, float bhn, float h)
{
    float r = sigf(giR + hsum(a[0]) + hsum(a[3]) + bhr);
    float z = sigf(giZ + hsum(a[1]) + hsum(a[4]) + bhz);
    float n = tanhf(giN + hsum(a[2]) + r * (hsum(a[5]) + bhn));
    return (1.f - z) * n + z * h;
}

// ---------------------------------------------------------------------------
// phase A: blocks 0..127 global GRU; blocks 128..143 attention context
// ---------------------------------------------------------------------------
__global__ void __launch_bounds__(128, 1) phaseA_kernel(int t,
    const float* __restrict__ Wih_g, const float* __restrict__ Whh_g,
    const float* __restrict__ bhh_g)
{
    __shared__ float al[TT * BB];     // attention branch only
    __shared__ float inv[BB];
    int bx = blockIdx.x, tid = threadIdx.x;
    int w = tid >> 5, lane = tid & 31;

    if (bx < 128) {
        int u0 = (bx * 4 + w) * 2, kp = u0 >> 1;
        const ull* hq = d_gh + (size_t)t * SLABQ;
        ull a[24];
        gru24(Wih_g, 2048, 1024, Whh_g, u0, lane, d_xA, hq, a);

        const float* gi = d_giU_g + (size_t)t * D3 * 64;
        float bh0r = bhh_g[u0],   bh0z = bhh_g[1024+u0],   bh0n = bhh_g[2048+u0];
        float bh1r = bhh_g[u0+1], bh1z = bhh_g[1024+u0+1], bh1n = bhh_g[2048+u0+1];
        ull* ghc = d_gh + (size_t)(t + 1) * SLABQ;
        #pragma unroll
        for (int bh = 0; bh < 2; bh++) {
            int b = lane + bh * 32;
            float h0, h1; upk2(hq[kp * 64 + b], h0, h1);
            float o0 = gout(a + bh*6,      gi[(size_t)u0*64+b], gi[(size_t)(1024+u0)*64+b],
                            gi[(size_t)(2048+u0)*64+b], bh0r, bh0z, bh0n, h0);
            float o1 = gout(a + 12 + bh*6, gi[(size_t)(u0+1)*64+b], gi[(size_t)(1025+u0)*64+b],
                            gi[(size_t)(2049+u0)*64+b], bh1r, bh1z, bh1n, h1);
            ghc[kp * 64 + b] = pk2(o0, o1);
        }
    } else {
        int kp0 = (bx - 128) * 32;                 // 16 blocks x 32 kp
        if (t == 0) {
            for (int i = tid; i < 2048; i += 128) d_ctx[kp0 * 64 + i] = 0ull;
            return;
        }
        if (tid < 64) {
            int b = tid;
            float mx = -3.0e38f;
            for (int tau = 0; tau < t; tau++)
                mx = fmaxf(mx, d_scores[tau * 64 + b]);
            float s = 0.f;
            for (int tau = 0; tau < t; tau++) {
                float e = __expf(d_scores[tau * 64 + b] - mx);
                al[tau * 64 + b] = e; s += e;
            }
            inv[b] = 1.f / s;
        }
        __syncthreads();
        int bb = (w & 1) * 32 + lane;
        int kpo = kp0 + (w >> 1) * 16;
        ull acc[16];
        #pragma unroll
        for (int j = 0; j < 16; j++) acc[j] = 0ull;
        for (int tau = 0; tau < t; tau++) {
            ull av = dup2(al[tau * 64 + bb]);
            const ull* g = d_gh + (size_t)(tau + 1) * SLABQ;
            #pragma unroll
            for (int j = 0; j < 16; j++)
                acc[j] = f2fma(av, g[(kpo + j) * 64 + bb], acc[j]);
        }
        ull iv = dup2(inv[bb]);
        #pragma unroll
        for (int j = 0; j < 16; j++)
            d_ctx[(kpo + j) * 64 + bb] = f2mul(acc[j], iv);
    }
}

// ---------------------------------------------------------------------------
// phase B: blocks 0..127 party GRU (speaker slot); block 128 score s_t
// ---------------------------------------------------------------------------
__global__ void __launch_bounds__(128, 1) phaseB_kernel(int t,
    const float* __restrict__ Wih_p, const float* __restrict__ Whh_p,
    const float* __restrict__ bhh_p, const float* __restrict__ w_att)
{
    int bx = blockIdx.x, tid = threadIdx.x;
    int w = tid >> 5, lane = tid & 31;

    if (bx < 128) {
        int u0 = (bx * 4 + w) * 2, kp = u0 >> 1;
        ull a[24];
        gru24(Wih_p, 2048, 1024, Whh_p, u0, lane, d_ctx, d_xA, a);

        const float* gi = d_giU_p + (size_t)t * D3 * 64;
        float bh0r = bhh_p[u0],   bh0z = bhh_p[1024+u0],   bh0n = bhh_p[2048+u0];
        float bh1r = bhh_p[u0+1], bh1z = bhh_p[1024+u0+1], bh1n = bhh_p[2048+u0+1];
        #pragma unroll
        for (int bh = 0; bh < 2; bh++) {
            int b = lane + bh * 32;
            float h0, h1; upk2(d_xA[kp * 64 + b], h0, h1);
            float o0 = gout(a + bh*6,      gi[(size_t)u0*64+b], gi[(size_t)(1024+u0)*64+b],
                            gi[(size_t)(2048+u0)*64+b], bh0r, bh0z, bh0n, h0);
            float o1 = gout(a + 12 + bh*6, gi[(size_t)(u0+1)*64+b], gi[(size_t)(1025+u0)*64+b],
                            gi[(size_t)(2049+u0)*64+b], bh1r, bh1z, bh1n, h1);
            d_qnew[kp * 64 + b] = pk2(o0, o1);
        }
    } else {
        __shared__ float part[128];
        int b = tid & 63, half = tid >> 6;
        const ull* g = d_gh + (size_t)(t + 1) * SLABQ;
        const ull* wq = (const ull*)w_att;
        ull acc = 0ull;
        for (int kp = half * 256; kp < half * 256 + 256; kp++)
            acc = f2fma(wq[kp], g[kp * 64 + b], acc);
        part[tid] = hsum(acc);
        __syncthreads();
        if (tid < 64) d_scores[t * 64 + tid] = part[tid] + part[64 + tid];
    }
}

// ---------------------------------------------------------------------------
// phase C: emotion GRU -> d_out; scatter qnew into parties; prep next xA
// ---------------------------------------------------------------------------
__global__ void __launch_bounds__(128, 1) phaseC_kernel(int t,
    const float* __restrict__ Wih_e, const float* __restrict__ Whh_e,
    const float* __restrict__ bih_e, const float* __restrict__ bhh_e,
    float* __restrict__ out)
{
    int bx = blockIdx.x, tid = threadIdx.x;
    int w = tid >> 5, lane = tid & 31;
    int u0 = (bx * 4 + w) * 2, kp = u0 >> 1;
    const ull* hq = d_ePI + (size_t)(t & 1) * SLABQ;
    ull* enew = d_ePI + (size_t)((t + 1) & 1) * SLABQ;
    ull a[24];
    gru24(Wih_e, 1024, 0, Whh_e, u0, lane, d_qnew, hq, a);

    float bi0r = bih_e[u0],   bi0z = bih_e[1024+u0],   bi0n = bih_e[2048+u0];
    float bi1r = bih_e[u0+1], bi1z = bih_e[1024+u0+1], bi1n = bih_e[2048+u0+1];
    float bh0r = bhh_e[u0],   bh0z = bhh_e[1024+u0],   bh0n = bhh_e[2048+u0];
    float bh1r = bhh_e[u0+1], bh1z = bhh_e[1024+u0+1], bh1n = bhh_e[2048+u0+1];

    #pragma unroll
    for (int bh = 0; bh < 2; bh++) {
        int b = lane + bh * 32;
        float h0, h1; upk2(hq[kp * 64 + b], h0, h1);
        float o0 = gout(a + bh*6,      bi0r, bi0z, bi0n, bh0r, bh0z, bh0n, h0);
        float o1 = gout(a + 12 + bh*6, bi1r, bi1z, bi1n, bh1r, bh1z, bh1n, h1);
        enew[kp * 64 + b] = pk2(o0, o1);
        *(ull*)(out + (size_t)t * BB * DD + (size_t)b * DD + u0) = pk2(o0, o1);

        // party scatter + next-step speaker gather (cell (kp,b) owned by this thread)
        ull qv = d_qnew[kp * 64 + b];
        int s0 = d_spk[t * 64 + b];
        d_par[(size_t)s0 * SLABQ + kp * 64 + b] = qv;
        if (t + 1 < TT) {
            int s1 = d_spk[(t + 1) * 64 + b];
            d_xA[kp * 64 + b] = (s1 == s0) ? qv : d_par[(size_t)s1 * SLABQ + kp * 64 + b];
        }
    }
}

// ---------------------------------------------------------------------------
extern "C" void kernel_launch(void* const* d_in, const int* in_sizes, int n_in,
                              void* d_out, int out_size)
{
    const float* features = (const float*)d_in[0];
    const float* speakers = (const float*)d_in[1];
    const float* Wih_g = (const float*)d_in[2];
    const float* Whh_g = (const float*)d_in[3];
    const float* bih_g = (const float*)d_in[4];
    const float* bhh_g = (const float*)d_in[5];
    const float* Wih_p = (const float*)d_in[6];
    const float* Whh_p = (const float*)d_in[7];
    const float* bih_p = (const float*)d_in[8];
    const float* bhh_p = (const float*)d_in[9];
    const float* Wih_e = (const float*)d_in[10];
    const float* Whh_e = (const float*)d_in[11];
    const float* bih_e = (const float*)d_in[12];
    const float* bhh_e = (const float*)d_in[13];
    const float* w_att = (const float*)d_in[14];
    float* out = (float*)d_out;

    init_kernel<<<640, 256>>>(speakers);

    dim3 pg(24, 64, 2);
    precompute_kernel<<<pg, 256>>>(features, Wih_g, bih_g, Wih_p, bih_p);

    for (int t = 0; t < TT; t++) {
        phaseA_kernel<<<144, 128>>>(t, Wih_g, Whh_g, bhh_g);
        phaseB_kernel<<<129, 128>>>(t, Wih_p, Whh_p, bhh_p, w_att);
        phaseC_kernel<<<128, 128>>>(t, Wih_e, Whh_e, bih_e, bhh_e, out);
    }
}

// round 5
// speedup vs baseline: 1.2066x; 1.2066x over previous
#include <cuda_runtime.h>
#include <cuda_bf16.h>
#include <math.h>

typedef unsigned long long ull;

#define TT 128
#define BB 64
#define SS 2
#define DD 1024
#define D3 3072
#define SLABQ 32768          /* ull per state slab: [512 kp][64 b] */

// state in PI layout: pair p of dims (2p,2p+1) at [p][b], packed float2-in-ull
__device__ float d_giU_g[(size_t)TT * D3 * BB];   // [t][j][b], bih included
__device__ float d_giU_p[(size_t)TT * D3 * BB];
__device__ ull   d_gh[(size_t)(TT + 1) * SLABQ];  // slab 0 zeros, slab t+1 = g_t
__device__ ull   d_xA[SLABQ];                     // party[speaker_t] (pre-update)
__device__ ull   d_ctx[SLABQ];
__device__ ull   d_qnew[SLABQ];
__device__ ull   d_ePI[2 * SLABQ];                // emotion ping-pong
__device__ ull   d_par[SS * SLABQ];               // party slots
__device__ float d_scores[TT * BB];
__device__ int   d_spk[TT * BB];

__device__ __forceinline__ ull pk2(float lo, float hi) {
    ull r; asm("mov.b64 %0, {%1, %2};" : "=l"(r) : "f"(lo), "f"(hi)); return r;
}
__device__ __forceinline__ ull dup2(float v) { return pk2(v, v); }
__device__ __forceinline__ void upk2(ull v, float& lo, float& hi) {
    asm("mov.b64 {%0, %1}, %2;" : "=f"(lo), "=f"(hi) : "l"(v));
}
__device__ __forceinline__ ull f2fma(ull a, ull b, ull c) {
    ull d; asm("fma.rn.f32x2 %0, %1, %2, %3;" : "=l"(d) : "l"(a), "l"(b), "l"(c)); return d;
}
__device__ __forceinline__ ull f2mul(ull a, ull b) {
    ull d; asm("mul.rn.f32x2 %0, %1, %2;" : "=l"(d) : "l"(a), "l"(b)); return d;
}
__device__ __forceinline__ float hsum(ull v) { float lo, hi; upk2(v, lo, hi); return lo + hi; }
__device__ __forceinline__ float sigf(float x) { return 1.f / (1.f + __expf(-x)); }

__device__ __forceinline__ unsigned smaddr(const void* p) {
    unsigned a;
    asm("{.reg .u64 t; cvta.to.shared.u64 t, %1; cvt.u32.u64 %0, t;}" : "=r"(a) : "l"(p));
    return a;
}
#define CPA16(dst, src) asm volatile("cp.async.ca.shared.global [%0], [%1], 16;" :: "r"(dst), "l"(src))
#define CPA_COMMIT()    asm volatile("cp.async.commit_group;")
#define CPA_WAIT1()     asm volatile("cp.async.wait_group 1;")
#define CPA_WAIT0()     asm volatile("cp.async.wait_group 0;")

// smem double buffer: per buffer  ws[48][16] ull (6144B) | ax[16][64] ull (8192B)
//                                 | ah[16][64] ull (8192B)  -> 22528B; x2 = 45056B
#define BUFB 22528

// ---------------------------------------------------------------------------
__global__ void init_kernel(const float* __restrict__ speakers) {
    int i = blockIdx.x * blockDim.x + threadIdx.x;      // 640*256 = 163840
    if (i < 32768) d_gh[i] = 0ull;
    else if (i < 65536) d_xA[i - 32768] = 0ull;
    else if (i < 98304) d_ePI[i - 65536] = 0ull;
    else if (i < 163840) d_par[i - 98304] = 0ull;
    if (i < TT * BB) {
        const float* sp = speakers + (size_t)i * SS;
        int best = 0; float bv = sp[0];
        #pragma unroll
        for (int s = 1; s < SS; s++) if (sp[s] > bv) { bv = sp[s]; best = s; }
        d_spk[i] = best;
    }
}

// ---------------------------------------------------------------------------
// precompute: out[t][j][b] = sum_k W[j][k]*X[t*64+b][k] + bias[j]   (unchanged)
// ---------------------------------------------------------------------------
__global__ void __launch_bounds__(256) precompute_kernel(
    const float* __restrict__ X,
    const float* __restrict__ Wg, const float* __restrict__ big,
    const float* __restrict__ Wp, const float* __restrict__ bip)
{
    const float* W    = blockIdx.z ? Wp : Wg;
    const float* bias = blockIdx.z ? bip : big;
    float* out        = blockIdx.z ? d_giU_p : d_giU_g;

    __shared__ float Ws[16][128];
    __shared__ float Xs[16][128];

    int tid = threadIdx.x;
    int tx = tid & 31, ty = tid >> 5;
    int j0 = blockIdx.x * 128;
    int r0 = blockIdx.y * 128;

    ull acc[8][4];
    #pragma unroll
    for (int p = 0; p < 8; p++)
        #pragma unroll
        for (int r = 0; r < 4; r++) acc[p][r] = 0ull;

    for (int k0 = 0; k0 < 1024; k0 += 16) {
        #pragma unroll
        for (int i = 0; i < 2; i++) {
            int f = tid * 2 + i;               // 0..511
            int rr = f >> 2, kc = (f & 3) * 4;
            float4 v = *(const float4*)&W[(size_t)(j0 + rr) * 2048 + k0 + kc];
            Ws[kc + 0][rr] = v.x; Ws[kc + 1][rr] = v.y;
            Ws[kc + 2][rr] = v.z; Ws[kc + 3][rr] = v.w;
            float4 u = *(const float4*)&X[(size_t)(r0 + rr) * 1024 + k0 + kc];
            Xs[kc + 0][rr] = u.x; Xs[kc + 1][rr] = u.y;
            Xs[kc + 2][rr] = u.z; Xs[kc + 3][rr] = u.w;
        }
        __syncthreads();
        #pragma unroll
        for (int k = 0; k < 16; k++) {
            ulonglong2 w0 = *(const ulonglong2*)&Ws[k][ty * 16 + 0];
            ulonglong2 w1 = *(const ulonglong2*)&Ws[k][ty * 16 + 4];
            ulonglong2 w2 = *(const ulonglong2*)&Ws[k][ty * 16 + 8];
            ulonglong2 w3 = *(const ulonglong2*)&Ws[k][ty * 16 + 12];
            ull wj[8] = {w0.x, w0.y, w1.x, w1.y, w2.x, w2.y, w3.x, w3.y};
            float4 xv = *(const float4*)&Xs[k][tx * 4];
            ull xx[4] = {dup2(xv.x), dup2(xv.y), dup2(xv.z), dup2(xv.w)};
            #pragma unroll
            for (int p = 0; p < 8; p++)
                #pragma unroll
                for (int r = 0; r < 4; r++)
                    acc[p][r] = f2fma(wj[p], xx[r], acc[p][r]);
        }
        __syncthreads();
    }
    int rbase = r0 + tx * 4;
    int tt = rbase >> 6, b0 = rbase & 63;
    #pragma unroll
    for (int p = 0; p < 8; p++) {
        int jj = j0 + ty * 16 + p * 2;
        float lo[4], hi[4];
        #pragma unroll
        for (int r = 0; r < 4; r++) upk2(acc[p][r], lo[r], hi[r]);
        float bl = bias[jj], bh = bias[jj + 1];
        float4 vlo = make_float4(lo[0]+bl, lo[1]+bl, lo[2]+bl, lo[3]+bl);
        float4 vhi = make_float4(hi[0]+bh, hi[1]+bh, hi[2]+bh, hi[3]+bh);
        *(float4*)&out[((size_t)tt * D3 + jj) * 64 + b0]       = vlo;
        *(float4*)&out[((size_t)tt * D3 + jj + 1) * 64 + b0]   = vhi;
    }
}

// ---------------------------------------------------------------------------
// smem-pipelined GRU core. Block: 128 thr = 4 warps, 8 units (ub..ub+7).
// Warp w: units ub+2w, ub+2w+1; lanes cover batches (lane, lane+32).
// acc[uu*12 + {0..2:x r,z,n | 3..5:h r,z,n}] for batch lane; +6 for lane+32.
// Weights+activations double-buffered via cp.async; 32 chunks of 32 k.
// ---------------------------------------------------------------------------
__device__ __forceinline__ void gru_core_smem(
    unsigned char* smbuf,
    const float* __restrict__ Wx, int wxs, int xoff,
    const float* __restrict__ Wh,
    int ub,
    const ull* __restrict__ xq, const ull* __restrict__ hq,
    ull* acc)
{
    const int tid = threadIdx.x;
    const int w = tid >> 5, lane = tid & 31;
    #pragma unroll
    for (int i = 0; i < 24; i++) acc[i] = 0ull;

    // weight staging descriptors: 3 x 16B per thread per chunk
    const float* wsrc[3];
    unsigned     wdst[3];
    #pragma unroll
    for (int i = 0; i < 3; i++) {
        int o = tid + 128 * i;            // 0..383
        int row = o >> 3, kpq = o & 7;    // row 0..47, 16B-group 0..7
        int g = row >> 3, uu = row & 7;
        const float* base = (g < 3)
            ? (Wx + (size_t)(g * 1024 + ub + uu) * wxs + xoff)
            : (Wh + (size_t)((g - 3) * 1024 + ub + uu) * 1024);
        wsrc[i] = base + kpq * 4;
        wdst[i] = row * 128 + kpq * 16;
    }
    // activation staging: 8 x 16B per thread per chunk (2 mats x 16 kp x 32 bpairs)
    const ull* asrc[8];
    unsigned   adst[8];
    #pragma unroll
    for (int i = 0; i < 8; i++) {
        int o = tid + 128 * i;            // 0..1023
        int m = o >> 9, r = o & 511, kp = r >> 5, bp = r & 31;
        asrc[i] = (m ? hq : xq) + kp * 64 + bp * 2;
        adst[i] = (m ? 14336u : 6144u) + kp * 512 + bp * 16;
    }
    unsigned sbase = smaddr(smbuf);

    // prologue: stage chunk 0 into buffer 0
    #pragma unroll
    for (int i = 0; i < 3; i++) CPA16(sbase + wdst[i], wsrc[i]);
    #pragma unroll
    for (int i = 0; i < 8; i++) CPA16(sbase + adst[i], asrc[i]);
    CPA_COMMIT();

    for (int c = 0; c < 32; c++) {
        if (c + 1 < 32) {
            unsigned bn = sbase + ((c + 1) & 1) * BUFB;
            #pragma unroll
            for (int i = 0; i < 3; i++) CPA16(bn + wdst[i], wsrc[i] + (c + 1) * 32);
            #pragma unroll
            for (int i = 0; i < 8; i++) CPA16(bn + adst[i], asrc[i] + (size_t)(c + 1) * 1024);
            CPA_COMMIT();
            CPA_WAIT1();
        } else {
            CPA_WAIT0();
        }
        __syncthreads();

        const ull* WS = (const ull*)(smbuf + (c & 1) * BUFB);   // [48][16]
        const ull* AX = WS + 768;                                // [16][64]
        const ull* AH = AX + 1024;
        int u0l = 2 * w;
        #pragma unroll
        for (int k2 = 0; k2 < 8; k2++) {
            ull x0a = AX[(2*k2)   * 64 + lane], x0b = AX[(2*k2)   * 64 + 32 + lane];
            ull x1a = AX[(2*k2+1) * 64 + lane], x1b = AX[(2*k2+1) * 64 + 32 + lane];
            ull h0a = AH[(2*k2)   * 64 + lane], h0b = AH[(2*k2)   * 64 + 32 + lane];
            ull h1a = AH[(2*k2+1) * 64 + lane], h1b = AH[(2*k2+1) * 64 + 32 + lane];
            #pragma unroll
            for (int uu = 0; uu < 2; uu++) {
                #pragma unroll
                for (int g = 0; g < 3; g++) {
                    ulonglong2 wx = *(const ulonglong2*)&WS[((g    ) * 8 + u0l + uu) * 16 + 2 * k2];
                    ulonglong2 wh = *(const ulonglong2*)&WS[((3 + g) * 8 + u0l + uu) * 16 + 2 * k2];
                    acc[uu*12 + g]     = f2fma(wx.x, x0a, acc[uu*12 + g]);
                    acc[uu*12 + g]     = f2fma(wx.y, x1a, acc[uu*12 + g]);
                    acc[uu*12 + 6 + g] = f2fma(wx.x, x0b, acc[uu*12 + 6 + g]);
                    acc[uu*12 + 6 + g] = f2fma(wx.y, x1b, acc[uu*12 + 6 + g]);
                    acc[uu*12 + 3 + g] = f2fma(wh.x, h0a, acc[uu*12 + 3 + g]);
                    acc[uu*12 + 3 + g] = f2fma(wh.y, h1a, acc[uu*12 + 3 + g]);
                    acc[uu*12 + 9 + g] = f2fma(wh.x, h0b, acc[uu*12 + 9 + g]);
                    acc[uu*12 + 9 + g] = f2fma(wh.y, h1b, acc[uu*12 + 9 + g]);
                }
            }
        }
        __syncthreads();
    }
}

// gate math; giR/Z/N already include x-projection + bih (phases A/B) or = bih (C)
__device__ __forceinline__ float gout(const ull* a, float giR, float giZ, float giN,
                                      float bhr, float bhz, float bhn, float h)
{
    float r = sigf(giR + hsum(a[0]) + hsum(a[3]) + bhr);
    float z = sigf(giZ + hsum(a[1]) + hsum(a[4]) + bhz);
    float n = tanhf(giN + hsum(a[2]) + r * (hsum(a[5]) + bhn));
    return (1.f - z) * n + z * h;
}

// ---------------------------------------------------------------------------
// phase A: blocks 0..127 global GRU; blocks 128..143 attention context
// ---------------------------------------------------------------------------
__global__ void __launch_bounds__(128, 1) phaseA_kernel(int t,
    const float* __restrict__ Wih_g, const float* __restrict__ Whh_g,
    const float* __restrict__ bhh_g)
{
    __shared__ __align__(16) unsigned char smbuf[2 * BUFB];
    int bx = blockIdx.x, tid = threadIdx.x;
    int w = tid >> 5, lane = tid & 31;

    if (bx < 128) {
        int ub = bx * 8;
        int u0 = ub + 2 * w, kp = u0 >> 1;
        const ull* hq = d_gh + (size_t)t * SLABQ;
        ull a[24];
        gru_core_smem(smbuf, Wih_g, 2048, 1024, Whh_g, ub, d_xA, hq, a);

        const float* gi = d_giU_g + (size_t)t * D3 * 64;
        float bh0r = bhh_g[u0],   bh0z = bhh_g[1024+u0],   bh0n = bhh_g[2048+u0];
        float bh1r = bhh_g[u0+1], bh1z = bhh_g[1024+u0+1], bh1n = bhh_g[2048+u0+1];
        ull* ghc = d_gh + (size_t)(t + 1) * SLABQ;
        #pragma unroll
        for (int bh = 0; bh < 2; bh++) {
            int b = lane + bh * 32;
            float h0, h1; upk2(hq[kp * 64 + b], h0, h1);
            float o0 = gout(a + bh*6,      gi[(size_t)u0*64+b], gi[(size_t)(1024+u0)*64+b],
                            gi[(size_t)(2048+u0)*64+b], bh0r, bh0z, bh0n, h0);
            float o1 = gout(a + 12 + bh*6, gi[(size_t)(u0+1)*64+b], gi[(size_t)(1025+u0)*64+b],
                            gi[(size_t)(2049+u0)*64+b], bh1r, bh1z, bh1n, h1);
            ghc[kp * 64 + b] = pk2(o0, o1);
        }
    } else {
        float* al  = (float*)smbuf;            // [t][64] unnormalized exp (<=32KB)
        float* inv = (float*)(smbuf + 32768);
        int kp0 = (bx - 128) * 32;             // 16 blocks x 32 kp
        if (t == 0) {
            for (int i = tid; i < 2048; i += 128) d_ctx[kp0 * 64 + i] = 0ull;
            return;
        }
        if (tid < 64) {
            int b = tid;
            float mx = -3.0e38f;
            for (int tau = 0; tau < t; tau++)
                mx = fmaxf(mx, d_scores[tau * 64 + b]);
            float s = 0.f;
            for (int tau = 0; tau < t; tau++) {
                float e = __expf(d_scores[tau * 64 + b] - mx);
                al[tau * 64 + b] = e; s += e;
            }
            inv[b] = 1.f / s;
        }
        __syncthreads();
        int bb = (w & 1) * 32 + lane;
        int kpo = kp0 + (w >> 1) * 16;
        ull acc[16];
        #pragma unroll
        for (int j = 0; j < 16; j++) acc[j] = 0ull;
        for (int tau = 0; tau < t; tau++) {
            ull av = dup2(al[tau * 64 + bb]);
            const ull* g = d_gh + (size_t)(tau + 1) * SLABQ;
            #pragma unroll
            for (int j = 0; j < 16; j++)
                acc[j] = f2fma(av, g[(kpo + j) * 64 + bb], acc[j]);
        }
        ull iv = dup2(inv[bb]);
        #pragma unroll
        for (int j = 0; j < 16; j++)
            d_ctx[(kpo + j) * 64 + bb] = f2mul(acc[j], iv);
    }
}

// ---------------------------------------------------------------------------
// phase B: blocks 0..127 party GRU (speaker slot); block 128 score s_t
// ---------------------------------------------------------------------------
__global__ void __launch_bounds__(128, 1) phaseB_kernel(int t,
    const float* __restrict__ Wih_p, const float* __restrict__ Whh_p,
    const float* __restrict__ bhh_p, const float* __restrict__ w_att)
{
    __shared__ __align__(16) unsigned char smbuf[2 * BUFB];
    int bx = blockIdx.x, tid = threadIdx.x;
    int w = tid >> 5, lane = tid & 31;

    if (bx < 128) {
        int ub = bx * 8;
        int u0 = ub + 2 * w, kp = u0 >> 1;
        ull a[24];
        gru_core_smem(smbuf, Wih_p, 2048, 1024, Whh_p, ub, d_ctx, d_xA, a);

        const float* gi = d_giU_p + (size_t)t * D3 * 64;
        float bh0r = bhh_p[u0],   bh0z = bhh_p[1024+u0],   bh0n = bhh_p[2048+u0];
        float bh1r = bhh_p[u0+1], bh1z = bhh_p[1024+u0+1], bh1n = bhh_p[2048+u0+1];
        #pragma unroll
        for (int bh = 0; bh < 2; bh++) {
            int b = lane + bh * 32;
            float h0, h1; upk2(d_xA[kp * 64 + b], h0, h1);
            float o0 = gout(a + bh*6,      gi[(size_t)u0*64+b], gi[(size_t)(1024+u0)*64+b],
                            gi[(size_t)(2048+u0)*64+b], bh0r, bh0z, bh0n, h0);
            float o1 = gout(a + 12 + bh*6, gi[(size_t)(u0+1)*64+b], gi[(size_t)(1025+u0)*64+b],
                            gi[(size_t)(2049+u0)*64+b], bh1r, bh1z, bh1n, h1);
            d_qnew[kp * 64 + b] = pk2(o0, o1);
        }
    } else {
        float* part = (float*)smbuf;
        int b = tid & 63, half = tid >> 6;
        const ull* g = d_gh + (size_t)(t + 1) * SLABQ;
        const ull* wq = (const ull*)w_att;
        ull acc = 0ull;
        for (int kp = half * 256; kp < half * 256 + 256; kp++)
            acc = f2fma(wq[kp], g[kp * 64 + b], acc);
        part[tid] = hsum(acc);
        __syncthreads();
        if (tid < 64) d_scores[t * 64 + tid] = part[tid] + part[64 + tid];
    }
}

// ---------------------------------------------------------------------------
// phase C: emotion GRU -> d_out; scatter qnew into parties; prep next xA
// ---------------------------------------------------------------------------
__global__ void __launch_bounds__(128, 1) phaseC_kernel(int t,
    const float* __restrict__ Wih_e, const float* __restrict__ Whh_e,
    const float* __restrict__ bih_e, const float* __restrict__ bhh_e,
    float* __restrict__ out)
{
    __shared__ __align__(16) unsigned char smbuf[2 * BUFB];
    int bx = blockIdx.x, tid = threadIdx.x;
    int w = tid >> 5, lane = tid & 31;
    int ub = bx * 8;
    int u0 = ub + 2 * w, kp = u0 >> 1;
    const ull* hq = d_ePI + (size_t)(t & 1) * SLABQ;
    ull* enew = d_ePI + (size_t)((t + 1) & 1) * SLABQ;
    ull a[24];
    gru_core_smem(smbuf, Wih_e, 1024, 0, Whh_e, ub, d_qnew, hq, a);

    float bi0r = bih_e[u0],   bi0z = bih_e[1024+u0],   bi0n = bih_e[2048+u0];
    float bi1r = bih_e[u0+1], bi1z = bih_e[1024+u0+1], bi1n = bih_e[2048+u0+1];
    float bh0r = bhh_e[u0],   bh0z = bhh_e[1024+u0],   bh0n = bhh_e[2048+u0];
    float bh1r = bhh_e[u0+1], bh1z = bhh_e[1024+u0+1], bh1n = bhh_e[2048+u0+1];

    #pragma unroll
    for (int bh = 0; bh < 2; bh++) {
        int b = lane + bh * 32;
        float h0, h1; upk2(hq[kp * 64 + b], h0, h1);
        float o0 = gout(a + bh*6,      bi0r, bi0z, bi0n, bh0r, bh0z, bh0n, h0);
        float o1 = gout(a + 12 + bh*6, bi1r, bi1z, bi1n, bh1r, bh1z, bh1n, h1);
        enew[kp * 64 + b] = pk2(o0, o1);
        *(ull*)(out + (size_t)t * BB * DD + (size_t)b * DD + u0) = pk2(o0, o1);

        // party scatter + next-step speaker gather (cell (kp,b) owned by this thread)
        ull qv = d_qnew[kp * 64 + b];
        int s0 = d_spk[t * 64 + b];
        d_par[(size_t)s0 * SLABQ + kp * 64 + b] = qv;
        if (t + 1 < TT) {
            int s1 = d_spk[(t + 1) * 64 + b];
            d_xA[kp * 64 + b] = (s1 == s0) ? qv : d_par[(size_t)s1 * SLABQ + kp * 64 + b];
        }
    }
}

// ---------------------------------------------------------------------------
extern "C" void kernel_launch(void* const* d_in, const int* in_sizes, int n_in,
                              void* d_out, int out_size)
{
    const float* features = (const float*)d_in[0];
    const float* speakers = (const float*)d_in[1];
    const float* Wih_g = (const float*)d_in[2];
    const float* Whh_g = (const float*)d_in[3];
    const float* bih_g = (const float*)d_in[4];
    const float* bhh_g = (const float*)d_in[5];
    const float* Wih_p = (const float*)d_in[6];
    const float* Whh_p = (const float*)d_in[7];
    const float* bih_p = (const float*)d_in[8];
    const float* bhh_p = (const float*)d_in[9];
    const float* Wih_e = (const float*)d_in[10];
    const float* Whh_e = (const float*)d_in[11];
    const float* bih_e = (const float*)d_in[12];
    const float* bhh_e = (const float*)d_in[13];
    const float* w_att = (const float*)d_in[14];
    float* out = (float*)d_out;

    init_kernel<<<640, 256>>>(speakers);

    dim3 pg(24, 64, 2);
    precompute_kernel<<<pg, 256>>>(features, Wih_g, bih_g, Wih_p, bih_p);

    for (int t = 0; t < TT; t++) {
        phaseA_kernel<<<144, 128>>>(t, Wih_g, Whh_g, bhh_g);
        phaseB_kernel<<<129, 128>>>(t, Wih_p, Whh_p, bhh_p, w_att);
        phaseC_kernel<<<128, 128>>>(t, Wih_e, Whh_e, bih_e, bhh_e, out);
    }
}

// round 16
// speedup vs baseline: 2.0146x; 1.6696x over previous
#include <cuda_runtime.h>
#include <cuda_bf16.h>
#include <math.h>

typedef unsigned long long ull;

#define TT 128
#define BB 64
#define SS 2
#define DD 1024
#define D3 3072
#define SLABQ 32768          /* ull per state slab: [512 kp][64 b] */

// state in PI layout: pair p of dims (2p,2p+1) at [p][b], packed float2-in-ull
__device__ float d_giU_g[(size_t)TT * D3 * BB];   // [t][j][b], bih included
__device__ float d_giU_p[(size_t)TT * D3 * BB];
__device__ ull   d_gh[(size_t)(TT + 1) * SLABQ];  // slab 0 zeros, slab t+1 = g_t
__device__ ull   d_xA[SLABQ];                     // party[speaker_t] (pre-update)
__device__ ull   d_ctx[SLABQ];
__device__ ull   d_qnew[SLABQ];
__device__ ull   d_ePI[2 * SLABQ];                // emotion ping-pong
__device__ ull   d_par[SS * SLABQ];               // party slots
__device__ float d_scores[TT * BB];
__device__ int   d_spk[TT * BB];

__device__ __forceinline__ ull pk2(float lo, float hi) {
    ull r; asm("mov.b64 %0, {%1, %2};" : "=l"(r) : "f"(lo), "f"(hi)); return r;
}
__device__ __forceinline__ ull dup2(float v) { return pk2(v, v); }
__device__ __forceinline__ void upk2(ull v, float& lo, float& hi) {
    asm("mov.b64 {%0, %1}, %2;" : "=f"(lo), "=f"(hi) : "l"(v));
}
__device__ __forceinline__ ull f2fma(ull a, ull b, ull c) {
    ull d; asm("fma.rn.f32x2 %0, %1, %2, %3;" : "=l"(d) : "l"(a), "l"(b), "l"(c)); return d;
}
__device__ __forceinline__ ull f2mul(ull a, ull b) {
    ull d; asm("mul.rn.f32x2 %0, %1, %2;" : "=l"(d) : "l"(a), "l"(b)); return d;
}
__device__ __forceinline__ float hsum(ull v) { float lo, hi; upk2(v, lo, hi); return lo + hi; }
__device__ __forceinline__ float sigf(float x) { return 1.f / (1.f + __expf(-x)); }

__device__ __forceinline__ unsigned smaddr(const void* p) {
    unsigned a;
    asm("{.reg .u64 t; cvta.to.shared.u64 t, %1; cvt.u32.u64 %0, t;}" : "=r"(a) : "l"(p));
    return a;
}
#define CPA16(dst, src) asm volatile("cp.async.ca.shared.global [%0], [%1], 16;" :: "r"(dst), "l"(src))
#define CPA_COMMIT()    asm volatile("cp.async.commit_group;")
#define CPA_WAIT1()     asm volatile("cp.async.wait_group 1;")
#define CPA_WAIT0()     asm volatile("cp.async.wait_group 0;")

// smem per buffer: ws[48][16] ull (6144B) | ax[16][64] ull (8192B) | ah[16][64] ull (8192B)
#define BUFB 22528

// ---------------------------------------------------------------------------
__global__ void init_kernel(const float* __restrict__ speakers) {
    int i = blockIdx.x * blockDim.x + threadIdx.x;      // 640*256 = 163840
    if (i < 32768) d_gh[i] = 0ull;
    else if (i < 65536) d_xA[i - 32768] = 0ull;
    else if (i < 98304) d_ePI[i - 65536] = 0ull;
    else if (i < 163840) d_par[i - 98304] = 0ull;
    if (i < TT * BB) {
        const float* sp = speakers + (size_t)i * SS;
        int best = 0; float bv = sp[0];
        #pragma unroll
        for (int s = 1; s < SS; s++) if (sp[s] > bv) { bv = sp[s]; best = s; }
        d_spk[i] = best;
    }
}

// ---------------------------------------------------------------------------
// precompute: out[t][j][b] = sum_k W[j][k]*X[t*64+b][k] + bias[j]
// ---------------------------------------------------------------------------
__global__ void __launch_bounds__(256) precompute_kernel(
    const float* __restrict__ X,
    const float* __restrict__ Wg, const float* __restrict__ big,
    const float* __restrict__ Wp, const float* __restrict__ bip)
{
    const float* W    = blockIdx.z ? Wp : Wg;
    const float* bias = blockIdx.z ? bip : big;
    float* out        = blockIdx.z ? d_giU_p : d_giU_g;

    __shared__ float Ws[16][128];
    __shared__ float Xs[16][128];

    int tid = threadIdx.x;
    int tx = tid & 31, ty = tid >> 5;
    int j0 = blockIdx.x * 128;
    int r0 = blockIdx.y * 128;

    ull acc[8][4];
    #pragma unroll
    for (int p = 0; p < 8; p++)
        #pragma unroll
        for (int r = 0; r < 4; r++) acc[p][r] = 0ull;

    for (int k0 = 0; k0 < 1024; k0 += 16) {
        #pragma unroll
        for (int i = 0; i < 2; i++) {
            int f = tid * 2 + i;               // 0..511
            int rr = f >> 2, kc = (f & 3) * 4;
            float4 v = *(const float4*)&W[(size_t)(j0 + rr) * 2048 + k0 + kc];
            Ws[kc + 0][rr] = v.x; Ws[kc + 1][rr] = v.y;
            Ws[kc + 2][rr] = v.z; Ws[kc + 3][rr] = v.w;
            float4 u = *(const float4*)&X[(size_t)(r0 + rr) * 1024 + k0 + kc];
            Xs[kc + 0][rr] = u.x; Xs[kc + 1][rr] = u.y;
            Xs[kc + 2][rr] = u.z; Xs[kc + 3][rr] = u.w;
        }
        __syncthreads();
        #pragma unroll
        for (int k = 0; k < 16; k++) {
            ulonglong2 w0 = *(const ulonglong2*)&Ws[k][ty * 16 + 0];
            ulonglong2 w1 = *(const ulonglong2*)&Ws[k][ty * 16 + 4];
            ulonglong2 w2 = *(const ulonglong2*)&Ws[k][ty * 16 + 8];
            ulonglong2 w3 = *(const ulonglong2*)&Ws[k][ty * 16 + 12];
            ull wj[8] = {w0.x, w0.y, w1.x, w1.y, w2.x, w2.y, w3.x, w3.y};
            float4 xv = *(const float4*)&Xs[k][tx * 4];
            ull xx[4] = {dup2(xv.x), dup2(xv.y), dup2(xv.z), dup2(xv.w)};
            #pragma unroll
            for (int p = 0; p < 8; p++)
                #pragma unroll
                for (int r = 0; r < 4; r++)
                    acc[p][r] = f2fma(wj[p], xx[r], acc[p][r]);
        }
        __syncthreads();
    }
    int rbase = r0 + tx * 4;
    int tt = rbase >> 6, b0 = rbase & 63;
    #pragma unroll
    for (int p = 0; p < 8; p++) {
        int jj = j0 + ty * 16 + p * 2;
        float lo[4], hi[4];
        #pragma unroll
        for (int r = 0; r < 4; r++) upk2(acc[p][r], lo[r], hi[r]);
        float bl = bias[jj], bh = bias[jj + 1];
        float4 vlo = make_float4(lo[0]+bl, lo[1]+bl, lo[2]+bl, lo[3]+bl);
        float4 vhi = make_float4(hi[0]+bh, hi[1]+bh, hi[2]+bh, hi[3]+bh);
        *(float4*)&out[((size_t)tt * D3 + jj) * 64 + b0]       = vlo;
        *(float4*)&out[((size_t)tt * D3 + jj + 1) * 64 + b0]   = vhi;
    }
}

// ---------------------------------------------------------------------------
// smem-pipelined GRU core, 256 thr / 8 warps. Warps 0-3: x-matrix gates for
// unit pair (w); warps 4-7: h-matrix gates for unit pair (w-4). Same staged
// chunks feed both groups. acc[(uu*2+bh)*3+g], 12 per warp. After the loop,
// h-warps deposit their sums in smbuf[0..12KB) for the matching x-warp.
// ---------------------------------------------------------------------------
__device__ __forceinline__ void gru_core_smem(
    unsigned char* smbuf,
    const float* __restrict__ Wx, int wxs, int xoff,
    const float* __restrict__ Wh,
    int ub,
    const ull* __restrict__ xq, const ull* __restrict__ hq,
    ull* acc)
{
    const int tid = threadIdx.x;
    const int w = tid >> 5, lane = tid & 31;
    #pragma unroll
    for (int i = 0; i < 12; i++) acc[i] = 0ull;

    // weight staging: 384 x 16B per chunk; thread: o=tid, plus o=256+tid if tid<128
    const float* wsrcA; unsigned wdstA;
    {
        int o = tid, row = o >> 3, kpq = o & 7;
        int g = row >> 3, uu = row & 7;
        const float* base = (g < 3)
            ? (Wx + (size_t)(g * 1024 + ub + uu) * wxs + xoff)
            : (Wh + (size_t)((g - 3) * 1024 + ub + uu) * 1024);
        wsrcA = base + kpq * 4; wdstA = row * 128 + kpq * 16;
    }
    const float* wsrcB = 0; unsigned wdstB = 0;
    if (tid < 128) {
        int o = 256 + tid, row = o >> 3, kpq = o & 7;
        int g = row >> 3, uu = row & 7;
        const float* base = (g < 3)
            ? (Wx + (size_t)(g * 1024 + ub + uu) * wxs + xoff)
            : (Wh + (size_t)((g - 3) * 1024 + ub + uu) * 1024);
        wsrcB = base + kpq * 4; wdstB = row * 128 + kpq * 16;
    }
    // activation staging: 1024 x 16B per chunk; 4 per thread
    const ull* asrc[4]; unsigned adst[4];
    #pragma unroll
    for (int j = 0; j < 4; j++) {
        int o = tid + 256 * j;
        int m = o >> 9, r = o & 511, kp = r >> 5, bp = r & 31;
        asrc[j] = (m ? hq : xq) + kp * 64 + bp * 2;
        adst[j] = 6144u + m * 8192u + kp * 512 + bp * 16;
    }
    unsigned sbase = smaddr(smbuf);

    // prologue: chunk 0 -> buffer 0
    CPA16(sbase + wdstA, wsrcA);
    if (tid < 128) CPA16(sbase + wdstB, wsrcB);
    #pragma unroll
    for (int j = 0; j < 4; j++) CPA16(sbase + adst[j], asrc[j]);
    CPA_COMMIT();

    const int mat = w >> 2;            // 0 = x-warps, 1 = h-warps
    const int u0l = 2 * (w & 3);

    for (int c = 0; c < 32; c++) {
        if (c + 1 < 32) {
            unsigned bn = sbase + ((c + 1) & 1) * BUFB;
            CPA16(bn + wdstA, wsrcA + (c + 1) * 32);
            if (tid < 128) CPA16(bn + wdstB, wsrcB + (c + 1) * 32);
            #pragma unroll
            for (int j = 0; j < 4; j++) CPA16(bn + adst[j], asrc[j] + (size_t)(c + 1) * 1024);
            CPA_COMMIT();
            CPA_WAIT1();
        } else {
            CPA_WAIT0();
        }
        __syncthreads();

        const ull* WS = (const ull*)(smbuf + (c & 1) * BUFB) + (size_t)mat * 384;
        const ull* A  = (const ull*)(smbuf + (c & 1) * BUFB) + 768 + (size_t)mat * 1024;
        #pragma unroll
        for (int k2 = 0; k2 < 8; k2++) {
            ull a0a = A[(2*k2)   * 64 + lane], a0b = A[(2*k2)   * 64 + 32 + lane];
            ull a1a = A[(2*k2+1) * 64 + lane], a1b = A[(2*k2+1) * 64 + 32 + lane];
            #pragma unroll
            for (int uu = 0; uu < 2; uu++) {
                #pragma unroll
                for (int g = 0; g < 3; g++) {
                    ulonglong2 wv = *(const ulonglong2*)&WS[(g * 8 + u0l + uu) * 16 + 2 * k2];
                    acc[(uu*2+0)*3+g] = f2fma(wv.x, a0a, acc[(uu*2+0)*3+g]);
                    acc[(uu*2+0)*3+g] = f2fma(wv.y, a1a, acc[(uu*2+0)*3+g]);
                    acc[(uu*2+1)*3+g] = f2fma(wv.x, a0b, acc[(uu*2+1)*3+g]);
                    acc[(uu*2+1)*3+g] = f2fma(wv.y, a1b, acc[(uu*2+1)*3+g]);
                }
            }
        }
        __syncthreads();
    }
    // handoff: h-warps deposit sums (buffer0 region is dead now)
    ull* hand = (ull*)smbuf;
    if (mat == 1) {
        #pragma unroll
        for (int j = 0; j < 12; j++)
            hand[((w - 4) * 32 + lane) * 12 + j] = acc[j];
    }
    __syncthreads();
}

__device__ __forceinline__ float gate3(float sxr, float sxz, float sxn,
                                       float shr, float shz, float shn,
                                       float giR, float giZ, float giN,
                                       float bhr, float bhz, float bhn, float h)
{
    float r = sigf(giR + sxr + shr + bhr);
    float z = sigf(giZ + sxz + shz + bhz);
    float n = tanhf(giN + sxn + r * (shn + bhn));
    return (1.f - z) * n + z * h;
}

// ---------------------------------------------------------------------------
// phase A: blocks 0..127 global GRU; blocks 128..143 attention context
// ---------------------------------------------------------------------------
__global__ void __launch_bounds__(256, 1) phaseA_kernel(int t,
    const float* __restrict__ Wih_g, const float* __restrict__ Whh_g,
    const float* __restrict__ bhh_g)
{
    __shared__ __align__(16) unsigned char smbuf[2 * BUFB];
    int bx = blockIdx.x, tid = threadIdx.x;
    int w = tid >> 5, lane = tid & 31;

    if (bx < 128) {
        int ub = bx * 8;
        const ull* hq = d_gh + (size_t)t * SLABQ;
        ull a[12];
        gru_core_smem(smbuf, Wih_g, 2048, 1024, Whh_g, ub, d_xA, hq, a);

        if (w < 4) {
            int u0 = ub + 2 * w, kp = u0 >> 1;
            const ull* hand = (const ull*)smbuf + ((size_t)w * 32 + lane) * 12;
            const float* gi = d_giU_g + (size_t)t * D3 * 64;
            float bh0r = bhh_g[u0],   bh0z = bhh_g[1024+u0],   bh0n = bhh_g[2048+u0];
            float bh1r = bhh_g[u0+1], bh1z = bhh_g[1024+u0+1], bh1n = bhh_g[2048+u0+1];
            ull* ghc = d_gh + (size_t)(t + 1) * SLABQ;
            #pragma unroll
            for (int bh = 0; bh < 2; bh++) {
                int b = lane + bh * 32;
                float h0, h1; upk2(hq[kp * 64 + b], h0, h1);
                float o0 = gate3(hsum(a[(0+bh)*3+0]), hsum(a[(0+bh)*3+1]), hsum(a[(0+bh)*3+2]),
                                 hsum(hand[(0+bh)*3+0]), hsum(hand[(0+bh)*3+1]), hsum(hand[(0+bh)*3+2]),
                                 gi[(size_t)u0*64+b], gi[(size_t)(1024+u0)*64+b], gi[(size_t)(2048+u0)*64+b],
                                 bh0r, bh0z, bh0n, h0);
                float o1 = gate3(hsum(a[(2+bh)*3+0]), hsum(a[(2+bh)*3+1]), hsum(a[(2+bh)*3+2]),
                                 hsum(hand[(2+bh)*3+0]), hsum(hand[(2+bh)*3+1]), hsum(hand[(2+bh)*3+2]),
                                 gi[(size_t)(u0+1)*64+b], gi[(size_t)(1025+u0)*64+b], gi[(size_t)(2049+u0)*64+b],
                                 bh1r, bh1z, bh1n, h1);
                ghc[kp * 64 + b] = pk2(o0, o1);
            }
        }
    } else {
        float* al  = (float*)smbuf;            // [t][64] unnormalized exp
        float* inv = (float*)(smbuf + 32768);
        int kp0 = (bx - 128) * 32;             // 16 blocks x 32 kp
        if (t == 0) {
            for (int i = tid; i < 2048; i += 256) d_ctx[kp0 * 64 + i] = 0ull;
            return;
        }
        if (tid < 64) {
            int b = tid;
            float mx = -3.0e38f;
            for (int tau = 0; tau < t; tau++)
                mx = fmaxf(mx, d_scores[tau * 64 + b]);
            float s = 0.f;
            for (int tau = 0; tau < t; tau++) {
                float e = __expf(d_scores[tau * 64 + b] - mx);
                al[tau * 64 + b] = e; s += e;
            }
            inv[b] = 1.f / s;
        }
        __syncthreads();
        int bb = (w & 1) * 32 + lane;
        int kpo = kp0 + (w >> 1) * 8;          // 8 warps: 4 kp-ranges x 2 halves
        ull acc[8];
        #pragma unroll
        for (int j = 0; j < 8; j++) acc[j] = 0ull;
        for (int tau = 0; tau < t; tau++) {
            ull av = dup2(al[tau * 64 + bb]);
            const ull* g = d_gh + (size_t)(tau + 1) * SLABQ;
            #pragma unroll
            for (int j = 0; j < 8; j++)
                acc[j] = f2fma(av, g[(kpo + j) * 64 + bb], acc[j]);
        }
        ull iv = dup2(inv[bb]);
        #pragma unroll
        for (int j = 0; j < 8; j++)
            d_ctx[(kpo + j) * 64 + bb] = f2mul(acc[j], iv);
    }
}

// ---------------------------------------------------------------------------
// phase B: blocks 0..127 party GRU (speaker slot); block 128 score s_t
// ---------------------------------------------------------------------------
__global__ void __launch_bounds__(256, 1) phaseB_kernel(int t,
    const float* __restrict__ Wih_p, const float* __restrict__ Whh_p,
    const float* __restrict__ bhh_p, const float* __restrict__ w_att)
{
    __shared__ __align__(16) unsigned char smbuf[2 * BUFB];
    int bx = blockIdx.x, tid = threadIdx.x;
    int w = tid >> 5, lane = tid & 31;

    if (bx < 128) {
        int ub = bx * 8;
        ull a[12];
        gru_core_smem(smbuf, Wih_p, 2048, 1024, Whh_p, ub, d_ctx, d_xA, a);

        if (w < 4) {
            int u0 = ub + 2 * w, kp = u0 >> 1;
            const ull* hand = (const ull*)smbuf + ((size_t)w * 32 + lane) * 12;
            const float* gi = d_giU_p + (size_t)t * D3 * 64;
            float bh0r = bhh_p[u0],   bh0z = bhh_p[1024+u0],   bh0n = bhh_p[2048+u0];
            float bh1r = bhh_p[u0+1], bh1z = bhh_p[1024+u0+1], bh1n = bhh_p[2048+u0+1];
            #pragma unroll
            for (int bh = 0; bh < 2; bh++) {
                int b = lane + bh * 32;
                float h0, h1; upk2(d_xA[kp * 64 + b], h0, h1);
                float o0 = gate3(hsum(a[(0+bh)*3+0]), hsum(a[(0+bh)*3+1]), hsum(a[(0+bh)*3+2]),
                                 hsum(hand[(0+bh)*3+0]), hsum(hand[(0+bh)*3+1]), hsum(hand[(0+bh)*3+2]),
                                 gi[(size_t)u0*64+b], gi[(size_t)(1024+u0)*64+b], gi[(size_t)(2048+u0)*64+b],
                                 bh0r, bh0z, bh0n, h0);
                float o1 = gate3(hsum(a[(2+bh)*3+0]), hsum(a[(2+bh)*3+1]), hsum(a[(2+bh)*3+2]),
                                 hsum(hand[(2+bh)*3+0]), hsum(hand[(2+bh)*3+1]), hsum(hand[(2+bh)*3+2]),
                                 gi[(size_t)(u0+1)*64+b], gi[(size_t)(1025+u0)*64+b], gi[(size_t)(2049+u0)*64+b],
                                 bh1r, bh1z, bh1n, h1);
                d_qnew[kp * 64 + b] = pk2(o0, o1);
            }
        }
    } else {
        float* part = (float*)smbuf;
        int b = tid & 63, q = tid >> 6;
        const ull* g = d_gh + (size_t)(t + 1) * SLABQ;
        const ull* wq = (const ull*)w_att;
        ull acc = 0ull;
        for (int kp = q * 128; kp < q * 128 + 128; kp++)
            acc = f2fma(wq[kp], g[kp * 64 + b], acc);
        part[tid] = hsum(acc);
        __syncthreads();
        if (tid < 64)
            d_scores[t * 64 + tid] = part[tid] + part[64 + tid] + part[128 + tid] + part[192 + tid];
    }
}

// ---------------------------------------------------------------------------
// phase C: emotion GRU -> d_out; scatter qnew into parties; prep next xA
// ---------------------------------------------------------------------------
__global__ void __launch_bounds__(256, 1) phaseC_kernel(int t,
    const float* __restrict__ Wih_e, const float* __restrict__ Whh_e,
    const float* __restrict__ bih_e, const float* __restrict__ bhh_e,
    float* __restrict__ out)
{
    __shared__ __align__(16) unsigned char smbuf[2 * BUFB];
    int bx = blockIdx.x, tid = threadIdx.x;
    int w = tid >> 5, lane = tid & 31;
    int ub = bx * 8;
    const ull* hq = d_ePI + (size_t)(t & 1) * SLABQ;
    ull* enew = d_ePI + (size_t)((t + 1) & 1) * SLABQ;
    ull a[12];
    gru_core_smem(smbuf, Wih_e, 1024, 0, Whh_e, ub, d_qnew, hq, a);

    if (w < 4) {
        int u0 = ub + 2 * w, kp = u0 >> 1;
        const ull* hand = (const ull*)smbuf + ((size_t)w * 32 + lane) * 12;
        float bi0r = bih_e[u0],   bi0z = bih_e[1024+u0],   bi0n = bih_e[2048+u0];
        float bi1r = bih_e[u0+1], bi1z = bih_e[1024+u0+1], bi1n = bih_e[2048+u0+1];
        float bh0r = bhh_e[u0],   bh0z = bhh_e[1024+u0],   bh0n = bhh_e[2048+u0];
        float bh1r = bhh_e[u0+1], bh1z = bhh_e[1024+u0+1], bh1n = bhh_e[2048+u0+1];

        #pragma unroll
        for (int bh = 0; bh < 2; bh++) {
            int b = lane + bh * 32;
            float h0, h1; upk2(hq[kp * 64 + b], h0, h1);
            float o0 = gate3(hsum(a[(0+bh)*3+0]), hsum(a[(0+bh)*3+1]), hsum(a[(0+bh)*3+2]),
                             hsum(hand[(0+bh)*3+0]), hsum(hand[(0+bh)*3+1]), hsum(hand[(0+bh)*3+2]),
                             bi0r, bi0z, bi0n, bh0r, bh0z, bh0n, h0);
            float o1 = gate3(hsum(a[(2+bh)*3+0]), hsum(a[(2+bh)*3+1]), hsum(a[(2+bh)*3+2]),
                             hsum(hand[(2+bh)*3+0]), hsum(hand[(2+bh)*3+1]), hsum(hand[(2+bh)*3+2]),
                             bi1r, bi1z, bi1n, bh1r, bh1z, bh1n, h1);
            enew[kp * 64 + b] = pk2(o0, o1);
            *(ull*)(out + (size_t)t * BB * DD + (size_t)b * DD + u0) = pk2(o0, o1);

            ull qv = d_qnew[kp * 64 + b];
            int s0 = d_spk[t * 64 + b];
            d_par[(size_t)s0 * SLABQ + kp * 64 + b] = qv;
            if (t + 1 < TT) {
                int s1 = d_spk[(t + 1) * 64 + b];
                d_xA[kp * 64 + b] = (s1 == s0) ? qv : d_par[(size_t)s1 * SLABQ + kp * 64 + b];
            }
        }
    }
}

// ---------------------------------------------------------------------------
extern "C" void kernel_launch(void* const* d_in, const int* in_sizes, int n_in,
                              void* d_out, int out_size)
{
    const float* features = (const float*)d_in[0];
    const float* speakers = (const float*)d_in[1];
    const float* Wih_g = (const float*)d_in[2];
    const float* Whh_g = (const float*)d_in[3];
    const float* bih_g = (const float*)d_in[4];
    const float* bhh_g = (const float*)d_in[5];
    const float* Wih_p = (const float*)d_in[6];
    const float* Whh_p = (const float*)d_in[7];
    const float* bih_p = (const float*)d_in[8];
    const float* bhh_p = (const float*)d_in[9];
    const float* Wih_e = (const float*)d_in[10];
    const float* Whh_e = (const float*)d_in[11];
    const float* bih_e = (const float*)d_in[12];
    const float* bhh_e = (const float*)d_in[13];
    const float* w_att = (const float*)d_in[14];
    float* out = (float*)d_out;

    init_kernel<<<640, 256>>>(speakers);

    dim3 pg(24, 64, 2);
    precompute_kernel<<<pg, 256>>>(features, Wih_g, bih_g, Wih_p, bih_p);

    for (int t = 0; t < TT; t++) {
        phaseA_kernel<<<144, 256>>>(t, Wih_g, Whh_g, bhh_g);
        phaseB_kernel<<<129, 256>>>(t, Wih_p, Whh_p, bhh_p, w_att);
        phaseC_kernel<<<128, 256>>>(t, Wih_e, Whh_e, bih_e, bhh_e, out);
    }
}